// round 9
// baseline (speedup 1.0000x reference)
#include <cuda_runtime.h>
#include <math.h>

constexpr int H_ = 1024, G_ = 4096, B_ = 32, T_ = 64, S_ = 64, L_ = 2;
constexpr int KP  = 256;           // k per pass
constexpr int XST = 268;           // smem row stride (floats)
constexpr int BUF = 8592;          // floats per buffer
constexpr int SMEM_BYTES = 4 * BUF * 4;   // 137472 B
constexpr int NBLK = 128;          // persistent grid
constexpr int NGRP = 8;            // barrier sub-groups (16 blocks each)

// Scratch (device globals)
__device__ float g_pre0[(size_t)T_ * G_ * B_];   // [t][j][b]
__device__ float g_ct[(size_t)B_ * S_ * H_];     // contexts @ W_in^T  [b][s][j]
__device__ float g_cbias[B_][S_];                // contexts . b_in
__device__ float g_hbuf[2][L_][B_][H_];
__device__ float g_c[L_][B_][H_];
__device__ float g_ctx[B_][H_];
__device__ unsigned g_cnt_sub[NGRP * 32];        // padded sub-counters
__device__ unsigned g_cnt_top;
__device__ volatile unsigned g_gen;

__device__ __forceinline__ float sigf(float x) { return 1.f / (1.f + expf(-x)); }
__device__ __forceinline__ unsigned su32(const void* p) {
    return (unsigned)__cvta_generic_to_shared(p);
}
__device__ __forceinline__ float unpack_sum(unsigned long long u) {
    float lo, hi;
    asm("mov.b64 {%0,%1}, %2;" : "=f"(lo), "=f"(hi) : "l"(u));
    return lo + hi;
}
#define FMA2(a, x, w) asm("fma.rn.f32x2 %0, %1, %2, %0;" : "+l"(a) : "l"(x), "l"(w))

__device__ __forceinline__ void mb_init(unsigned long long* m) {
    asm volatile("mbarrier.init.shared.b64 [%0], 1;" :: "r"(su32(m)) : "memory");
}
__device__ __forceinline__ void mb_expect(unsigned mb, unsigned bytes) {
    asm volatile("mbarrier.arrive.expect_tx.shared.b64 _, [%0], %1;"
                 :: "r"(mb), "r"(bytes) : "memory");
}
__device__ __forceinline__ void mb_wait(unsigned mb, unsigned par) {
    asm volatile(
        "{\n\t.reg .pred P;\n\tW1_%=:\n\t"
        "mbarrier.try_wait.parity.acquire.cta.shared::cta.b64 P, [%0], %1, 0x989680;\n\t"
        "@P bra.uni W2_%=;\n\tbra.uni W1_%=;\n\tW2_%=:\n\t}"
        :: "r"(mb), "r"(par) : "memory");
}
__device__ __forceinline__ void bulk1k(unsigned dst, const float* src, unsigned mb) {
    asm volatile(
        "cp.async.bulk.shared::cta.global.mbarrier::complete_tx::bytes [%0], [%1], 1024, [%2];"
        :: "r"(dst), "l"(src), "r"(mb) : "memory");
}

// Hierarchical grid barrier: 16 arrivals per sub-counter, 8 sub -> master.
__device__ __forceinline__ void grid_bar() {
    __syncthreads();
    if (threadIdx.x == 0) {
        __threadfence();
        unsigned gen = g_gen;
        if (atomicInc(&g_cnt_sub[(blockIdx.x & (NGRP - 1)) * 32],
                      NBLK / NGRP - 1) == NBLK / NGRP - 1) {
            if (atomicInc(&g_cnt_top, NGRP - 1) == NGRP - 1) g_gen = gen + 1;
        }
        while (g_gen == gen) __nanosleep(32);
        __threadfence();
    }
    __syncthreads();
}

__device__ __forceinline__ int skw(int r) { return ((r >> 3) & 3) * 4; }

// ---------------------------------------------------------------------------
// Stage one pass into (xb, wb): 32 x-rows + nw w-rows, 1KB bulk copies.
// Weight smem row r -> global row j0 + (r&7) + (r>>3)*GS.
// ---------------------------------------------------------------------------
template <bool GATHER>
__device__ __forceinline__ void stage(int nw, float* xb, float* wb, unsigned mb,
                                      const float* __restrict__ X, const int* toks,
                                      const float* __restrict__ W, size_t ldw,
                                      int j0, int GS, int k0, int tid) {
    if (tid == 0) mb_expect(mb, (unsigned)(32 + nw) * 1024u);
    __syncthreads();
    if (tid < 32) {
        const float* src = GATHER ? X + (size_t)toks[tid] * H_ + k0
                                  : X + (size_t)tid * H_ + k0;
        bulk1k(su32(xb + tid * XST + skw(tid)), src, mb);
    } else if (tid < 32 + nw) {
        int r = tid - 32;
        bulk1k(su32(wb + r * XST + skw(r)),
               W + (size_t)(j0 + (r & 7) + (r >> 3) * GS) * ldw + k0, mb);
    }
}

// ---------------------------------------------------------------------------
// 32-row GEMM: warp = (ks = wid&3 k-slice, rh = wid>>2 row half);
// thread tile = 8 rows x 2 batches; acc[16] f32x2.
// ---------------------------------------------------------------------------
template <bool GATHER>
__device__ __forceinline__ void gemm32(float* sm, const unsigned* mbs, unsigned* ph,
                                       const float* __restrict__ X, const int* toks,
                                       const float* __restrict__ W, size_t ldw,
                                       int j0, int GS, int NPK,
                                       unsigned long long* acc,
                                       int tid, int wid, int lane) {
    float* xb[2] = {sm, sm + 2 * BUF};
    float* wb[2] = {sm + BUF, sm + 3 * BUF};
    const int ks = wid & 3, rh = wid >> 2;
    const int bp = lane & 15, rg = lane >> 4;
    const int R0 = rh * 16 + rg * 8;
    stage<GATHER>(32, xb[0], wb[0], mbs[0], X, toks, W, ldw, j0, GS, 0, tid);
    stage<GATHER>(32, xb[1], wb[1], mbs[1], X, toks, W, ldw, j0, GS, KP, tid);
    for (int p = 0; p < NPK; p++) {
        int s = p & 1;
        mb_wait(mbs[s], ph[s] & 1);
        ph[s]++;
        const float* xp0 = xb[s] + (2 * bp) * XST + skw(2 * bp) + ks * 64;
        const float* wp  = wb[s] + R0 * XST + skw(R0) + ks * 64;
#pragma unroll 2
        for (int kq = 0; kq < 64; kq += 4) {
            ulonglong2 x0 = *(const ulonglong2*)(xp0 + kq);
            ulonglong2 x1 = *(const ulonglong2*)(xp0 + XST + kq);
#pragma unroll
            for (int r = 0; r < 8; r++) {
                ulonglong2 wv = *(const ulonglong2*)(wp + r * XST + kq);
                FMA2(acc[2 * r],     x0.x, wv.x); FMA2(acc[2 * r],     x0.y, wv.y);
                FMA2(acc[2 * r + 1], x1.x, wv.x); FMA2(acc[2 * r + 1], x1.y, wv.y);
            }
        }
        if (p + 2 < NPK)
            stage<GATHER>(32, xb[s], wb[s], mbs[s], X, toks, W, ldw, j0, GS,
                          (p + 2) * KP, tid);
    }
}

// ---------------------------------------------------------------------------
// 8-row GEMM: warp = k-slice of 32, lanes = (kk sub-slice of 16, bp batch-pair)
// ---------------------------------------------------------------------------
__device__ __forceinline__ void gemm8(float* sm, const unsigned* mbs, unsigned* ph,
                                      const float* __restrict__ X,
                                      const float* __restrict__ W, size_t ldw,
                                      int j0, int NPK, unsigned long long* acc,
                                      int tid, int wid, int lane) {
    float* xb[2] = {sm, sm + 2 * BUF};
    float* wb[2] = {sm + BUF, sm + 3 * BUF};
    const int bp = lane & 15, kk = lane >> 4;
    stage<false>(8, xb[0], wb[0], mbs[0], X, nullptr, W, ldw, j0, 8, 0, tid);
    stage<false>(8, xb[1], wb[1], mbs[1], X, nullptr, W, ldw, j0, 8, KP, tid);
    for (int p = 0; p < NPK; p++) {
        int s = p & 1;
        mb_wait(mbs[s], ph[s] & 1);
        ph[s]++;
        const int ko = wid * 32 + kk * 16;
        const float* xp0 = xb[s] + (2 * bp) * XST + skw(2 * bp) + ko;
        const float* wp  = wb[s] + ko;
#pragma unroll
        for (int kq = 0; kq < 16; kq += 4) {
            ulonglong2 x0 = *(const ulonglong2*)(xp0 + kq);
            ulonglong2 x1 = *(const ulonglong2*)(xp0 + XST + kq);
#pragma unroll
            for (int r = 0; r < 8; r++) {
                ulonglong2 wv = *(const ulonglong2*)(wp + r * XST + kq);
                FMA2(acc[2 * r],     x0.x, wv.x); FMA2(acc[2 * r],     x0.y, wv.y);
                FMA2(acc[2 * r + 1], x1.x, wv.x); FMA2(acc[2 * r + 1], x1.y, wv.y);
            }
        }
        if (p + 2 < NPK)
            stage<false>(8, xb[s], wb[s], mbs[s], X, nullptr, W, ldw, j0, 8,
                         (p + 2) * KP, tid);
    }
}

// Partial-sum reductions via smem
__device__ __forceinline__ void red_write32(float* red, const unsigned long long* acc,
                                            int wid, int lane) {
    const int ks = wid & 3, rh = wid >> 2, bp = lane & 15, rg = lane >> 4;
    const int R0 = rh * 16 + rg * 8;
#pragma unroll
    for (int r = 0; r < 8; r++) {
        float2 v = make_float2(unpack_sum(acc[2 * r]), unpack_sum(acc[2 * r + 1]));
        *(float2*)&red[ks * 1024 + (R0 + r) * 32 + 2 * bp] = v;
    }
}
__device__ __forceinline__ float red_sum32(const float* red, int row, int b) {
    return red[row * 32 + b] + red[1024 + row * 32 + b] +
           red[2048 + row * 32 + b] + red[3072 + row * 32 + b];
}
__device__ __forceinline__ void red_write8(float* red, const unsigned long long* acc,
                                           int wid, int lane) {
    const int bp = lane & 15, kk = lane >> 4;
    const int sl = wid * 2 + kk;
#pragma unroll
    for (int r = 0; r < 8; r++) {
        float2 v = make_float2(unpack_sum(acc[2 * r]), unpack_sum(acc[2 * r + 1]));
        *(float2*)&red[sl * 256 + r * 32 + 2 * bp] = v;
    }
}
__device__ __forceinline__ float red_sum8(const float* red, int row, int b) {
    float s = 0.f;
#pragma unroll
    for (int i = 0; i < 16; i++) s += red[i * 256 + row * 32 + b];
    return s;
}

// ===========================================================================
// Persistent step kernel. grid NBLK x 256.
// Per step: cell0 |BAR| cell1 |BAR| out_h1 + attn |BAR| out_ctx
// ===========================================================================
__global__ void __launch_bounds__(256, 1) k_steps(const float* __restrict__ Whh0,
                                                  const float* __restrict__ Wih1,
                                                  const float* __restrict__ Whh1,
                                                  const float* __restrict__ bih1,
                                                  const float* __restrict__ bhh1,
                                                  const float* __restrict__ W_out,
                                                  const float* __restrict__ b_out,
                                                  const float* __restrict__ contexts,
                                                  float* __restrict__ out) {
    extern __shared__ float sm[];
    __shared__ unsigned long long mbar[2];
    __shared__ float gs[H_];
    __shared__ float w_sh[S_];
    const int tid = threadIdx.x, wid = tid >> 5, lane = tid & 31;
    const int blk = blockIdx.x;
    const int jl = tid >> 5, b = tid & 31;
    const int j = blk * 8 + jl;

    if (tid == 0) { mb_init(&mbar[0]); mb_init(&mbar[1]); }
    __syncthreads();
    unsigned mbs[2] = {su32(&mbar[0]), su32(&mbar[1])};
    unsigned ph[2] = {0u, 0u};

    for (int t = 0; t < T_; t++) {
        const int cur = t & 1;

        // ---- cell0 ----
        {
            unsigned long long acc[16] = {};
            gemm32<false>(sm, mbs, ph, &g_hbuf[1 - cur][0][0][0], nullptr,
                          Whh0, H_, blk * 8, H_, 4, acc, tid, wid, lane);
            __syncthreads();
            red_write32(sm, acc, wid, lane);
            __syncthreads();
            const float* pre = g_pre0 + (size_t)t * G_ * B_;
            float v[4];
#pragma unroll
            for (int g = 0; g < 4; g++)
                v[g] = red_sum32(sm, g * 8 + jl, b) + pre[(size_t)(g * H_ + j) * B_ + b];
            float c1 = sigf(v[1]) * g_c[0][b][j] + sigf(v[0]) * tanhf(v[2]);
            g_c[0][b][j] = c1;
            g_hbuf[cur][0][b][j] = sigf(v[3]) * tanhf(c1);
        }
        grid_bar();

        // ---- cell1 ----
        {
            unsigned long long acc[16] = {};
            gemm32<false>(sm, mbs, ph, &g_hbuf[cur][0][0][0], nullptr,
                          Wih1, H_, blk * 8, H_, 4, acc, tid, wid, lane);
            gemm32<false>(sm, mbs, ph, &g_hbuf[1 - cur][1][0][0], nullptr,
                          Whh1, H_, blk * 8, H_, 4, acc, tid, wid, lane);
            __syncthreads();
            red_write32(sm, acc, wid, lane);
            __syncthreads();
            float v[4];
#pragma unroll
            for (int g = 0; g < 4; g++)
                v[g] = red_sum32(sm, g * 8 + jl, b) + bih1[g * H_ + j] + bhh1[g * H_ + j];
            float c1 = sigf(v[1]) * g_c[1][b][j] + sigf(v[0]) * tanhf(v[2]);
            g_c[1][b][j] = c1;
            g_hbuf[cur][1][b][j] = sigf(v[3]) * tanhf(c1);
        }
        grid_bar();

        // ---- phase 3: out (h1 half) for all blocks; attention on blocks 0..31 ----
        unsigned long long oacc[16] = {};
        gemm8(sm, mbs, ph, &g_hbuf[cur][1][0][0], W_out + H_, 2 * H_, blk * 8, 4,
              oacc, tid, wid, lane);
        if (blk < B_) {
            const int bb = blk;
            for (int i = tid; i < H_; i += 256) gs[i] = g_hbuf[cur][1][bb][i];
            __syncthreads();
            // scores[s] = Ct[bb][s][:] . h1[bb] + cbias[bb][s]
#pragma unroll
            for (int si = 0; si < S_ / 8; si++) {
                int s = wid * (S_ / 8) + si;
                const float* cp = g_ct + ((size_t)bb * S_ + s) * H_;
                float a = 0.f;
                for (int k = lane; k < H_; k += 32) a = fmaf(cp[k], gs[k], a);
#pragma unroll
                for (int o = 16; o; o >>= 1) a += __shfl_xor_sync(0xffffffffu, a, o);
                if (lane == 0) w_sh[s] = a + g_cbias[bb][s];
            }
            __syncthreads();
            if (wid == 0) {
                float v0 = w_sh[lane], v1 = w_sh[lane + 32];
                float m = fmaxf(v0, v1);
#pragma unroll
                for (int o = 16; o; o >>= 1) m = fmaxf(m, __shfl_xor_sync(0xffffffffu, m, o));
                float e0 = expf(v0 - m), e1 = expf(v1 - m);
                float ssum = e0 + e1;
#pragma unroll
                for (int o = 16; o; o >>= 1) ssum += __shfl_xor_sync(0xffffffffu, ssum, o);
                float inv = 1.f / ssum;
                w_sh[lane] = e0 * inv;
                w_sh[lane + 32] = e1 * inv;
            }
            __syncthreads();
#pragma unroll
            for (int i = 0; i < H_ / 256; i++) {
                int k = tid + i * 256;
                const float* cp = contexts + (size_t)bb * S_ * H_ + k;
                float a = 0.f;
#pragma unroll 8
                for (int s = 0; s < S_; s++) a = fmaf(w_sh[s], cp[(size_t)s * H_], a);
                g_ctx[bb][k] = a;
            }
        }
        grid_bar();

        // ---- phase 4: out (ctx half), accumulate into oacc, write out ----
        {
            gemm8(sm, mbs, ph, &g_ctx[0][0], W_out, 2 * H_, blk * 8, 4,
                  oacc, tid, wid, lane);
            __syncthreads();
            red_write8(sm, oacc, wid, lane);
            __syncthreads();
            out[(size_t)t * B_ * H_ + (size_t)b * H_ + j] =
                tanhf(red_sum8(sm, jl, b) + b_out[j]);
        }
        // no grid_bar: g_ctx rewritten only after 2 bars of step t+1
    }
}

// ===========================================================================
// pre0: grid (G/32, T) x 256. 32-row GEMM with embedding gather.
// ===========================================================================
__global__ void __launch_bounds__(256, 1) k_pre0(const int* __restrict__ tokens,
                                                 const float* __restrict__ emb,
                                                 const float* __restrict__ Wih0,
                                                 const float* __restrict__ bih0,
                                                 const float* __restrict__ bhh0) {
    extern __shared__ float sm[];
    __shared__ unsigned long long mbar[2];
    __shared__ int toks[B_];
    const int tid = threadIdx.x, wid = tid >> 5, lane = tid & 31;
    const int t = blockIdx.y;
    const int j0 = blockIdx.x * 32;

    if (tid == 0) { mb_init(&mbar[0]); mb_init(&mbar[1]); }
    if (tid < B_) toks[tid] = tokens[t * B_ + tid];
    __syncthreads();
    unsigned mbs[2] = {su32(&mbar[0]), su32(&mbar[1])};
    unsigned ph[2] = {0u, 0u};

    unsigned long long acc[16] = {};
    gemm32<true>(sm, mbs, ph, emb, toks, Wih0, H_, j0, 8, 4, acc, tid, wid, lane);
    __syncthreads();
    red_write32(sm, acc, wid, lane);
    __syncthreads();

    const int jl = tid >> 5, b = tid & 31;
#pragma unroll
    for (int i = 0; i < 4; i++) {
        int row = jl + i * 8;
        int jj = j0 + row;
        g_pre0[((size_t)t * G_ + jj) * B_ + b] =
            red_sum32(sm, row, b) + bih0[jj] + bhh0[jj];
    }
}

// ===========================================================================
// Ct[bs][j] = contexts[bs][:] . W_in[j][:]   (bs = b*S+s flattened, 2048 rows)
// grid (32 j-tiles, 64 bs-tiles) x 256
// ===========================================================================
__global__ void __launch_bounds__(256, 1) k_ctilde(const float* __restrict__ contexts,
                                                   const float* __restrict__ W_in) {
    extern __shared__ float sm[];
    __shared__ unsigned long long mbar[2];
    const int tid = threadIdx.x, wid = tid >> 5, lane = tid & 31;
    const int j0 = blockIdx.x * 32;
    const int bs0 = blockIdx.y * 32;

    if (tid == 0) { mb_init(&mbar[0]); mb_init(&mbar[1]); }
    __syncthreads();
    unsigned mbs[2] = {su32(&mbar[0]), su32(&mbar[1])};
    unsigned ph[2] = {0u, 0u};

    unsigned long long acc[16] = {};
    gemm32<false>(sm, mbs, ph, contexts + (size_t)bs0 * H_, nullptr,
                  W_in, H_, j0, 8, 4, acc, tid, wid, lane);
    __syncthreads();
    red_write32(sm, acc, wid, lane);
    __syncthreads();

    const int j_l = tid & 31;
#pragma unroll
    for (int i = 0; i < 4; i++) {
        int bs_l = (tid >> 5) + i * 8;
        g_ct[(size_t)(bs0 + bs_l) * H_ + j0 + j_l] = red_sum32(sm, j_l, bs_l);
    }
}

// cbias[b][s] = contexts[b][s][:] . b_in    grid B_ x 256
__global__ void __launch_bounds__(256) k_cbias(const float* __restrict__ contexts,
                                               const float* __restrict__ b_in) {
    const int tid = threadIdx.x, wid = tid >> 5, lane = tid & 31;
    const int b = blockIdx.x;
#pragma unroll
    for (int si = 0; si < S_ / 8; si++) {
        int s = wid * (S_ / 8) + si;
        const float* cp = contexts + ((size_t)b * S_ + s) * H_;
        float a = 0.f;
        for (int k = lane; k < H_; k += 32) a = fmaf(cp[k], b_in[k], a);
#pragma unroll
        for (int o = 16; o; o >>= 1) a += __shfl_xor_sync(0xffffffffu, a, o);
        if (lane == 0) g_cbias[b][s] = a;
    }
}

// ---------------------------------------------------------------------------
extern "C" void kernel_launch(void* const* d_in, const int* in_sizes, int n_in,
                              void* d_out, int out_size) {
    const int*   tokens   = (const int*)d_in[0];
    const float* h0       = (const float*)d_in[1];
    const float* c0       = (const float*)d_in[2];
    const float* contexts = (const float*)d_in[3];
    const float* emb      = (const float*)d_in[4];
    const float* W_ih     = (const float*)d_in[5];
    const float* W_hh     = (const float*)d_in[6];
    const float* b_ih     = (const float*)d_in[7];
    const float* b_hh     = (const float*)d_in[8];
    const float* W_in     = (const float*)d_in[9];
    const float* b_in     = (const float*)d_in[10];
    const float* W_out    = (const float*)d_in[11];
    const float* b_out    = (const float*)d_in[12];
    float* out = (float*)d_out;

    cudaFuncSetAttribute(k_pre0,   cudaFuncAttributeMaxDynamicSharedMemorySize, SMEM_BYTES);
    cudaFuncSetAttribute(k_steps,  cudaFuncAttributeMaxDynamicSharedMemorySize, SMEM_BYTES);
    cudaFuncSetAttribute(k_ctilde, cudaFuncAttributeMaxDynamicSharedMemorySize, SMEM_BYTES);

    const size_t stateBytes = (size_t)L_ * B_ * H_ * sizeof(float);

    // init state: h -> hbuf[1] (prev of t=0), c -> g_c
    cudaMemcpyToSymbolAsync(g_hbuf, h0, stateBytes, stateBytes,
                            cudaMemcpyDeviceToDevice, 0);
    cudaMemcpyToSymbolAsync(g_c, c0, stateBytes, 0, cudaMemcpyDeviceToDevice, 0);

    // hoisted precomputes
    k_pre0<<<dim3(G_ / 32, T_), 256, SMEM_BYTES>>>(tokens, emb, W_ih, b_ih, b_hh);
    k_ctilde<<<dim3(H_ / 32, (B_ * S_) / 32), 256, SMEM_BYTES>>>(contexts, W_in);
    k_cbias<<<B_, 256>>>(contexts, b_in);

    const float* Wih1 = W_ih + (size_t)G_ * H_;
    const float* Whh1 = W_hh + (size_t)G_ * H_;
    const float* bih1 = b_ih + G_;
    const float* bhh1 = b_hh + G_;

    // entire recurrence in ONE persistent kernel
    k_steps<<<NBLK, 256, SMEM_BYTES>>>(W_hh, Wih1, Whh1, bih1, bhh1,
                                       W_out, b_out, contexts, out);

    // hT (in hbuf[1] since (T-1)&1 == 1), then cT
    cudaMemcpyFromSymbolAsync(out + (size_t)T_ * B_ * H_, g_hbuf, stateBytes,
                              stateBytes, cudaMemcpyDeviceToDevice, 0);
    cudaMemcpyFromSymbolAsync(out + (size_t)T_ * B_ * H_ + (size_t)L_ * B_ * H_,
                              g_c, stateBytes, 0, cudaMemcpyDeviceToDevice, 0);
}

// round 10
// speedup vs baseline: 1.0721x; 1.0721x over previous
#include <cuda_runtime.h>
#include <math.h>

constexpr int H_ = 1024, G_ = 4096, B_ = 32, T_ = 64, S_ = 64, L_ = 2;
constexpr int KP  = 256;            // k per pass
constexpr int XST = 268;            // smem row stride (floats)
constexpr int BUF = 8608;           // floats per buffer
constexpr int REDF = 4096;          // reduction scratch floats
constexpr int SMEM_BYTES = (4 * BUF + REDF) * 4;   // 154112 B
constexpr int NBLK = 128;           // persistent grid
constexpr int NGRP = 8;             // barrier sub-groups

// Scratch (device globals)
__device__ float g_pre0[(size_t)T_ * G_ * B_];   // [t][j][b]
__device__ float g_hbuf[2][L_][B_][H_];
__device__ float g_c[L_][B_][H_];
__device__ float g_gamma[B_][H_];
__device__ float g_scores[B_][S_];
__device__ float g_ctx[B_][H_];
__device__ unsigned g_cnt_sub[NGRP * 32];
__device__ unsigned g_cnt_top;
__device__ volatile unsigned g_gen;

__device__ __forceinline__ float sigf(float x) { return 1.f / (1.f + expf(-x)); }
__device__ __forceinline__ unsigned su32(const void* p) {
    return (unsigned)__cvta_generic_to_shared(p);
}
__device__ __forceinline__ float unpack_sum(unsigned long long u) {
    float lo, hi;
    asm("mov.b64 {%0,%1}, %2;" : "=f"(lo), "=f"(hi) : "l"(u));
    return lo + hi;
}
#define FMA2(a, x, w) asm("fma.rn.f32x2 %0, %1, %2, %0;" : "+l"(a) : "l"(x), "l"(w))

__device__ __forceinline__ void mb_init(unsigned long long* m) {
    asm volatile("mbarrier.init.shared.b64 [%0], 1;" :: "r"(su32(m)) : "memory");
}
__device__ __forceinline__ void mb_expect(unsigned mb, unsigned bytes) {
    asm volatile("mbarrier.arrive.expect_tx.shared.b64 _, [%0], %1;"
                 :: "r"(mb), "r"(bytes) : "memory");
}
__device__ __forceinline__ void mb_wait(unsigned mb, unsigned par) {
    asm volatile(
        "{\n\t.reg .pred P;\n\tW1_%=:\n\t"
        "mbarrier.try_wait.parity.acquire.cta.shared::cta.b64 P, [%0], %1, 0x989680;\n\t"
        "@P bra.uni W2_%=;\n\tbra.uni W1_%=;\n\tW2_%=:\n\t}"
        :: "r"(mb), "r"(par) : "memory");
}
__device__ __forceinline__ void bulk1k(unsigned dst, const float* src, unsigned mb) {
    asm volatile(
        "cp.async.bulk.shared::cta.global.mbarrier::complete_tx::bytes [%0], [%1], 1024, [%2];"
        :: "r"(dst), "l"(src), "r"(mb) : "memory");
}

// Hierarchical grid barrier
__device__ __forceinline__ void grid_bar() {
    __syncthreads();
    if (threadIdx.x == 0) {
        __threadfence();
        unsigned gen = g_gen;
        if (atomicInc(&g_cnt_sub[(blockIdx.x & (NGRP - 1)) * 32],
                      NBLK / NGRP - 1) == NBLK / NGRP - 1) {
            if (atomicInc(&g_cnt_top, NGRP - 1) == NGRP - 1) g_gen = gen + 1;
        }
        while (g_gen == gen) __nanosleep(32);
        __threadfence();
    }
    __syncthreads();
}

__device__ __forceinline__ int skw(int r) { return ((r >> 3) & 7) * 4; }

// ---------------------------------------------------------------------------
// Job = one (possibly two-half) GEMM over K=1024 (or 2x1024 when npk==8).
// Pass p: half = p>=4 (only for npk==8), k0 = (p&3)*KP, buffer = p&1.
// Weight smem row r -> global row j0 + (r&7) + (r>>3)*GS.
// ---------------------------------------------------------------------------
struct Job {
    const float *Xa, *Xb, *Wa, *Wb;
    const int* toks;       // embedding gather (pre0) or nullptr
    size_t ldw;
    int j0, GS, nw, npk;
};
struct Bufs {
    float *xb0, *xb1, *wb0, *wb1;
    unsigned mb0, mb1;
};

__device__ __forceinline__ void stage_w(const Bufs& Bf, const Job& J, int p, int tid) {
    const int s = p & 1;
    const unsigned mb = s ? Bf.mb1 : Bf.mb0;
    float* wb = s ? Bf.wb1 : Bf.wb0;
    if (tid == 0) mb_expect(mb, (unsigned)(32 + J.nw) * 1024u);
    __syncthreads();   // all warps done reading this buffer pair
    if (tid >= 32 && tid < 32 + J.nw) {
        int r = tid - 32;
        const float* W = (p >= 4) ? J.Wb : J.Wa;
        int k0 = (p & 3) * KP;
        bulk1k(su32(wb + r * XST + skw(r)),
               W + (size_t)(J.j0 + (r & 7) + (r >> 3) * J.GS) * J.ldw + k0, mb);
    }
}
__device__ __forceinline__ void stage_x(const Bufs& Bf, const Job& J, int p, int tid) {
    const int s = p & 1;
    const unsigned mb = s ? Bf.mb1 : Bf.mb0;
    float* xb = s ? Bf.xb1 : Bf.xb0;
    if (tid < 32) {
        const float* X = (p >= 4) ? J.Xb : J.Xa;
        int k0 = (p & 3) * KP;
        const float* src = J.toks ? X + (size_t)J.toks[tid] * H_ + k0
                                  : X + (size_t)tid * H_ + k0;
        bulk1k(su32(xb + tid * XST + skw(tid)), src, mb);
    }
}

// 32-row compute: warp = (ks=wid&3 k-slice of 64, rh=wid>>2 row half);
// thread tile 8 rows x 2 batches.
__device__ __forceinline__ void comp32(const float* xb, const float* wb,
                                       unsigned long long* acc, int wid, int lane) {
    const int ks = wid & 3, rh = wid >> 2;
    const int bp = lane & 15, rg = lane >> 4;
    const int R0 = rh * 16 + rg * 8;
    const float* xp0 = xb + (2 * bp) * XST + skw(2 * bp) + ks * 64;
    const float* wp  = wb + R0 * XST + skw(R0) + ks * 64;
#pragma unroll 2
    for (int kq = 0; kq < 64; kq += 4) {
        ulonglong2 x0 = *(const ulonglong2*)(xp0 + kq);
        ulonglong2 x1 = *(const ulonglong2*)(xp0 + XST + kq);
#pragma unroll
        for (int r = 0; r < 8; r++) {
            ulonglong2 wv = *(const ulonglong2*)(wp + r * XST + kq);
            FMA2(acc[2 * r],     x0.x, wv.x); FMA2(acc[2 * r],     x0.y, wv.y);
            FMA2(acc[2 * r + 1], x1.x, wv.x); FMA2(acc[2 * r + 1], x1.y, wv.y);
        }
    }
}
// 8-row compute: warp = k-slice of 32, lane = (kk sub-slice of 16, bp pair)
__device__ __forceinline__ void comp8(const float* xb, const float* wb,
                                      unsigned long long* acc, int wid, int lane) {
    const int bp = lane & 15, kk = lane >> 4;
    const int ko = wid * 32 + kk * 16;
    const float* xp0 = xb + (2 * bp) * XST + skw(2 * bp) + ko;
    const float* wp  = wb + ko;
#pragma unroll
    for (int kq = 0; kq < 16; kq += 4) {
        ulonglong2 x0 = *(const ulonglong2*)(xp0 + kq);
        ulonglong2 x1 = *(const ulonglong2*)(xp0 + XST + kq);
#pragma unroll
        for (int r = 0; r < 8; r++) {
            ulonglong2 wv = *(const ulonglong2*)(wp + r * XST + kq);
            FMA2(acc[2 * r],     x0.x, wv.x); FMA2(acc[2 * r],     x0.y, wv.y);
            FMA2(acc[2 * r + 1], x1.x, wv.x); FMA2(acc[2 * r + 1], x1.y, wv.y);
        }
    }
}

// Run a job; during the last two passes prestage nextJ's passes 0,1
// (weights always; x only when nextX and its source is already published).
template <bool W32>
__device__ void run_job(const Bufs& Bf, const Job& J, const Job* nextJ, bool nextX,
                        unsigned long long* acc, unsigned* ph,
                        int tid, int wid, int lane) {
    for (int p = 0; p < J.npk; p++) {
        const int s = p & 1;
        const unsigned mb = s ? Bf.mb1 : Bf.mb0;
        mb_wait(mb, ph[s] & 1);
        ph[s]++;
        const float* xb = s ? Bf.xb1 : Bf.xb0;
        const float* wb = s ? Bf.wb1 : Bf.wb0;
        if (W32) comp32(xb, wb, acc, wid, lane);
        else     comp8(xb, wb, acc, wid, lane);
        if (p + 2 < J.npk) {
            stage_w(Bf, J, p + 2, tid);
            stage_x(Bf, J, p + 2, tid);
        } else if (nextJ) {
            int q = p + 2 - J.npk;
            stage_w(Bf, *nextJ, q, tid);
            if (nextX) stage_x(Bf, *nextJ, q, tid);
        }
    }
}

// Reductions (into dedicated red region)
__device__ __forceinline__ void red_write32(float* red, const unsigned long long* acc,
                                            int wid, int lane) {
    const int ks = wid & 3, rh = wid >> 2, bp = lane & 15, rg = lane >> 4;
    const int R0 = rh * 16 + rg * 8;
#pragma unroll
    for (int r = 0; r < 8; r++) {
        float2 v = make_float2(unpack_sum(acc[2 * r]), unpack_sum(acc[2 * r + 1]));
        *(float2*)&red[ks * 1024 + (R0 + r) * 32 + 2 * bp] = v;
    }
}
__device__ __forceinline__ float red_sum32(const float* red, int row, int b) {
    return red[row * 32 + b] + red[1024 + row * 32 + b] +
           red[2048 + row * 32 + b] + red[3072 + row * 32 + b];
}
__device__ __forceinline__ void red_write8(float* red, const unsigned long long* acc,
                                           int wid, int lane) {
    const int bp = lane & 15, kk = lane >> 4;
    const int sl = wid * 2 + kk;
#pragma unroll
    for (int r = 0; r < 8; r++) {
        float2 v = make_float2(unpack_sum(acc[2 * r]), unpack_sum(acc[2 * r + 1]));
        *(float2*)&red[sl * 256 + r * 32 + 2 * bp] = v;
    }
}
__device__ __forceinline__ float red_sum8(const float* red, int row, int b) {
    float s = 0.f;
#pragma unroll
    for (int i = 0; i < 16; i++) s += red[i * 256 + row * 32 + b];
    return s;
}

// ===========================================================================
// Persistent step kernel. grid NBLK x 256.
// Per step: cell0 |B| cell1 |B| gamma |B| scores+out_h1 |B| ctx |B| out_ctx
// ===========================================================================
__global__ void __launch_bounds__(256, 1) k_steps(const float* __restrict__ Whh0,
                                                  const float* __restrict__ Wih1,
                                                  const float* __restrict__ Whh1,
                                                  const float* __restrict__ bih1,
                                                  const float* __restrict__ bhh1,
                                                  const float* __restrict__ W_in,
                                                  const float* __restrict__ b_in,
                                                  const float* __restrict__ W_out,
                                                  const float* __restrict__ b_out,
                                                  const float* __restrict__ contexts,
                                                  float* __restrict__ out) {
    extern __shared__ float sm[];
    __shared__ unsigned long long mbar[2];
    __shared__ float gs[H_];
    __shared__ float w_sh[S_];
    const int tid = threadIdx.x, wid = tid >> 5, lane = tid & 31;
    const int blk = blockIdx.x;
    const int jl = tid >> 5, b = tid & 31;
    const int j = blk * 8 + jl;
    float* red = sm + 4 * BUF;

    if (tid == 0) { mb_init(&mbar[0]); mb_init(&mbar[1]); }
    __syncthreads();
    Bufs Bf = {sm, sm + 2 * BUF, sm + BUF, sm + 3 * BUF,
               su32(&mbar[0]), su32(&mbar[1])};
    unsigned ph[2] = {0u, 0u};

    // pre-loop: fully stage cell0(t=0) passes 0,1  (x = hbuf[1][0], ready)
    {
        Job C0 = {&g_hbuf[1][0][0][0], nullptr, Whh0, nullptr, nullptr,
                  (size_t)H_, blk * 8, H_, 32, 4};
        stage_w(Bf, C0, 0, tid); stage_x(Bf, C0, 0, tid);
        stage_w(Bf, C0, 1, tid); stage_x(Bf, C0, 1, tid);
    }

    for (int t = 0; t < T_; t++) {
        const int cur = t & 1;

        Job C0 = {&g_hbuf[1 - cur][0][0][0], nullptr, Whh0, nullptr, nullptr,
                  (size_t)H_, blk * 8, H_, 32, 4};
        Job C1 = {&g_hbuf[cur][0][0][0], &g_hbuf[1 - cur][1][0][0],
                  Wih1, Whh1, nullptr, (size_t)H_, blk * 8, H_, 32, 8};
        Job GM = {&g_hbuf[cur][1][0][0], nullptr, W_in, nullptr, nullptr,
                  (size_t)H_, blk * 8, 8, 8, 4};
        Job OA = {&g_hbuf[cur][1][0][0], nullptr, W_out + H_, nullptr, nullptr,
                  (size_t)(2 * H_), blk * 8, 8, 8, 4};
        Job OB = {&g_ctx[0][0], nullptr, W_out, nullptr, nullptr,
                  (size_t)(2 * H_), blk * 8, 8, 8, 4};
        Job C0n = {&g_hbuf[cur][0][0][0], nullptr, Whh0, nullptr, nullptr,
                   (size_t)H_, blk * 8, H_, 32, 4};

        // ---- P1: cell0 (already fully staged), prestage C1 weights ----
        {
            unsigned long long acc[16] = {};
            run_job<true>(Bf, C0, &C1, false, acc, ph, tid, wid, lane);
            red_write32(red, acc, wid, lane);
            __syncthreads();
            const float* pre = g_pre0 + (size_t)t * G_ * B_;
            float v[4];
#pragma unroll
            for (int g = 0; g < 4; g++)
                v[g] = red_sum32(red, g * 8 + jl, b) + pre[(size_t)(g * H_ + j) * B_ + b];
            float c1 = sigf(v[1]) * g_c[0][b][j] + sigf(v[0]) * tanhf(v[2]);
            g_c[0][b][j] = c1;
            g_hbuf[cur][0][b][j] = sigf(v[3]) * tanhf(c1);
        }
        grid_bar();

        // ---- P2: cell1 (x now published), prestage gamma weights ----
        {
            stage_x(Bf, C1, 0, tid);
            stage_x(Bf, C1, 1, tid);
            unsigned long long acc[16] = {};
            run_job<true>(Bf, C1, &GM, false, acc, ph, tid, wid, lane);
            red_write32(red, acc, wid, lane);
            __syncthreads();
            float v[4];
#pragma unroll
            for (int g = 0; g < 4; g++)
                v[g] = red_sum32(red, g * 8 + jl, b) + bih1[g * H_ + j] + bhh1[g * H_ + j];
            float c1 = sigf(v[1]) * g_c[1][b][j] + sigf(v[0]) * tanhf(v[2]);
            g_c[1][b][j] = c1;
            g_hbuf[cur][1][b][j] = sigf(v[3]) * tanhf(c1);
        }
        grid_bar();

        // ---- P3: gamma; prestage out_h1 fully (x = h1 is published) ----
        {
            stage_x(Bf, GM, 0, tid);
            stage_x(Bf, GM, 1, tid);
            unsigned long long acc[16] = {};
            run_job<false>(Bf, GM, &OA, true, acc, ph, tid, wid, lane);
            red_write8(red, acc, wid, lane);
            __syncthreads();
            g_gamma[b][j] = red_sum8(red, jl, b) + b_in[j];
        }
        grid_bar();

        // ---- P4: scores (all 128 blocks, 16 each) + out h1-half GEMM ----
        unsigned long long oacc[16] = {};
        {
            const int bb = blk & 31, sg = blk >> 5;
            for (int i = tid; i < H_; i += 256) gs[i] = g_gamma[bb][i];
            __syncthreads();
#pragma unroll
            for (int i = 0; i < 2; i++) {
                int s = sg * 16 + wid * 2 + i;
                const float* cp = contexts + ((size_t)bb * S_ + s) * H_;
                float a = 0.f;
                for (int k = lane; k < H_; k += 32) a = fmaf(cp[k], gs[k], a);
#pragma unroll
                for (int o = 16; o; o >>= 1) a += __shfl_xor_sync(0xffffffffu, a, o);
                if (lane == 0) g_scores[bb][s] = a;
            }
            run_job<false>(Bf, OA, &OB, false, oacc, ph, tid, wid, lane);
        }
        grid_bar();

        // ---- P5: softmax + ctx slice (4 blocks per b, 256 k each) ----
        {
            const int bb = blk & 31, kg = blk >> 5;
            if (wid == 0) {
                float v0 = g_scores[bb][lane], v1 = g_scores[bb][lane + 32];
                float m = fmaxf(v0, v1);
#pragma unroll
                for (int o = 16; o; o >>= 1) m = fmaxf(m, __shfl_xor_sync(0xffffffffu, m, o));
                float e0 = expf(v0 - m), e1 = expf(v1 - m);
                float ssum = e0 + e1;
#pragma unroll
                for (int o = 16; o; o >>= 1) ssum += __shfl_xor_sync(0xffffffffu, ssum, o);
                float inv = 1.f / ssum;
                w_sh[lane] = e0 * inv;
                w_sh[lane + 32] = e1 * inv;
            }
            __syncthreads();
            int k = kg * 256 + tid;
            const float* cp = contexts + (size_t)bb * S_ * H_ + k;
            float a = 0.f;
#pragma unroll 8
            for (int s = 0; s < S_; s++) a = fmaf(w_sh[s], cp[(size_t)s * H_], a);
            g_ctx[bb][k] = a;
        }
        grid_bar();

        // ---- P6: out ctx-half; prestage next cell0 fully; epilogue ----
        {
            stage_x(Bf, OB, 0, tid);
            stage_x(Bf, OB, 1, tid);
            run_job<false>(Bf, OB, (t + 1 < T_) ? &C0n : nullptr, true,
                           oacc, ph, tid, wid, lane);
            __syncthreads();
            red_write8(red, oacc, wid, lane);
            __syncthreads();
            out[(size_t)t * B_ * H_ + (size_t)b * H_ + j] =
                tanhf(red_sum8(red, jl, b) + b_out[j]);
        }
        // no grid_bar: C0n inputs published >=4 bars ago; g_ctx rewritten
        // only after multiple bars of step t+1.
    }
}

// ===========================================================================
// pre0: grid (G/32, T) x 256. 32-row GEMM with embedding gather.
// ===========================================================================
__global__ void __launch_bounds__(256, 1) k_pre0(const int* __restrict__ tokens,
                                                 const float* __restrict__ emb,
                                                 const float* __restrict__ Wih0,
                                                 const float* __restrict__ bih0,
                                                 const float* __restrict__ bhh0) {
    extern __shared__ float sm[];
    __shared__ unsigned long long mbar[2];
    __shared__ int toks[B_];
    const int tid = threadIdx.x, wid = tid >> 5, lane = tid & 31;
    const int t = blockIdx.y;
    const int j0 = blockIdx.x * 32;
    float* red = sm + 4 * BUF;

    if (tid == 0) { mb_init(&mbar[0]); mb_init(&mbar[1]); }
    if (tid < B_) toks[tid] = tokens[t * B_ + tid];
    __syncthreads();
    Bufs Bf = {sm, sm + 2 * BUF, sm + BUF, sm + 3 * BUF,
               su32(&mbar[0]), su32(&mbar[1])};
    unsigned ph[2] = {0u, 0u};

    Job P = {emb, nullptr, Wih0, nullptr, toks, (size_t)H_, j0, 8, 32, 4};
    stage_w(Bf, P, 0, tid); stage_x(Bf, P, 0, tid);
    stage_w(Bf, P, 1, tid); stage_x(Bf, P, 1, tid);

    unsigned long long acc[16] = {};
    run_job<true>(Bf, P, nullptr, false, acc, ph, tid, wid, lane);
    __syncthreads();
    red_write32(red, acc, wid, lane);
    __syncthreads();

    const int jl = tid >> 5, b = tid & 31;
#pragma unroll
    for (int i = 0; i < 4; i++) {
        int row = jl + i * 8;
        int jj = j0 + row;
        g_pre0[((size_t)t * G_ + jj) * B_ + b] =
            red_sum32(red, row, b) + bih0[jj] + bhh0[jj];
    }
}

// ---------------------------------------------------------------------------
extern "C" void kernel_launch(void* const* d_in, const int* in_sizes, int n_in,
                              void* d_out, int out_size) {
    const int*   tokens   = (const int*)d_in[0];
    const float* h0       = (const float*)d_in[1];
    const float* c0       = (const float*)d_in[2];
    const float* contexts = (const float*)d_in[3];
    const float* emb      = (const float*)d_in[4];
    const float* W_ih     = (const float*)d_in[5];
    const float* W_hh     = (const float*)d_in[6];
    const float* b_ih     = (const float*)d_in[7];
    const float* b_hh     = (const float*)d_in[8];
    const float* W_in     = (const float*)d_in[9];
    const float* b_in     = (const float*)d_in[10];
    const float* W_out    = (const float*)d_in[11];
    const float* b_out    = (const float*)d_in[12];
    float* out = (float*)d_out;

    cudaFuncSetAttribute(k_pre0,  cudaFuncAttributeMaxDynamicSharedMemorySize, SMEM_BYTES);
    cudaFuncSetAttribute(k_steps, cudaFuncAttributeMaxDynamicSharedMemorySize, SMEM_BYTES);

    const size_t stateBytes = (size_t)L_ * B_ * H_ * sizeof(float);

    // init state: h -> hbuf[1] (prev of t=0), c -> g_c
    cudaMemcpyToSymbolAsync(g_hbuf, h0, stateBytes, stateBytes,
                            cudaMemcpyDeviceToDevice, 0);
    cudaMemcpyToSymbolAsync(g_c, c0, stateBytes, 0, cudaMemcpyDeviceToDevice, 0);

    // hoisted layer-0 input projection for all timesteps
    k_pre0<<<dim3(G_ / 32, T_), 256, SMEM_BYTES>>>(tokens, emb, W_ih, b_ih, b_hh);

    const float* Wih1 = W_ih + (size_t)G_ * H_;
    const float* Whh1 = W_hh + (size_t)G_ * H_;
    const float* bih1 = b_ih + G_;
    const float* bhh1 = b_hh + G_;

    // entire recurrence in ONE persistent kernel
    k_steps<<<NBLK, 256, SMEM_BYTES>>>(W_hh, Wih1, Whh1, bih1, bhh1,
                                       W_in, b_in, W_out, b_out, contexts, out);

    // hT (in hbuf[1] since (T-1)&1 == 1), then cT
    cudaMemcpyFromSymbolAsync(out + (size_t)T_ * B_ * H_, g_hbuf, stateBytes,
                              stateBytes, cudaMemcpyDeviceToDevice, 0);
    cudaMemcpyFromSymbolAsync(out + (size_t)T_ * B_ * H_ + (size_t)L_ * B_ * H_,
                              g_c, stateBytes, 0, cudaMemcpyDeviceToDevice, 0);
}

// round 11
// speedup vs baseline: 1.1495x; 1.0723x over previous
#include <cuda_runtime.h>
#include <math.h>

constexpr int H_ = 1024, G_ = 4096, B_ = 32, T_ = 64, S_ = 64, L_ = 2;
constexpr int KP  = 256;            // k per pass
constexpr int XST = 268;            // smem row stride (floats)
constexpr int BUF = 8608;           // floats per buffer
constexpr int REDF = 8192;          // reduction scratch floats
constexpr int SMEM_BYTES = (4 * BUF + REDF) * 4;   // 170496 B
constexpr int NBLK = 128;           // persistent grid
constexpr int NGRP = 8;             // barrier sub-groups
constexpr int NT_ = 512;            // threads per block

// Scratch (device globals)
__device__ float g_pre0[(size_t)T_ * G_ * B_];   // [t][j][b]
__device__ float g_hbuf[2][L_][B_][H_];
__device__ float g_c[L_][B_][H_];
__device__ float g_gamma[B_][H_];
__device__ float g_ctx[B_][H_];
__device__ unsigned g_cnt_sub[NGRP * 32];
__device__ unsigned g_cnt_top;
__device__ volatile unsigned g_gen;

__device__ __forceinline__ float sigf(float x) { return 1.f / (1.f + expf(-x)); }
__device__ __forceinline__ unsigned su32(const void* p) {
    return (unsigned)__cvta_generic_to_shared(p);
}
__device__ __forceinline__ float unpack_sum(unsigned long long u) {
    float lo, hi;
    asm("mov.b64 {%0,%1}, %2;" : "=f"(lo), "=f"(hi) : "l"(u));
    return lo + hi;
}
#define FMA2(a, x, w) asm("fma.rn.f32x2 %0, %1, %2, %0;" : "+l"(a) : "l"(x), "l"(w))

__device__ __forceinline__ void mb_init(unsigned long long* m) {
    asm volatile("mbarrier.init.shared.b64 [%0], 1;" :: "r"(su32(m)) : "memory");
}
__device__ __forceinline__ void mb_expect(unsigned mb, unsigned bytes) {
    asm volatile("mbarrier.arrive.expect_tx.shared.b64 _, [%0], %1;"
                 :: "r"(mb), "r"(bytes) : "memory");
}
__device__ __forceinline__ void mb_wait(unsigned mb, unsigned par) {
    asm volatile(
        "{\n\t.reg .pred P;\n\tW1_%=:\n\t"
        "mbarrier.try_wait.parity.acquire.cta.shared::cta.b64 P, [%0], %1, 0x989680;\n\t"
        "@P bra.uni W2_%=;\n\tbra.uni W1_%=;\n\tW2_%=:\n\t}"
        :: "r"(mb), "r"(par) : "memory");
}
__device__ __forceinline__ void bulk1k(unsigned dst, const float* src, unsigned mb) {
    asm volatile(
        "cp.async.bulk.shared::cta.global.mbarrier::complete_tx::bytes [%0], [%1], 1024, [%2];"
        :: "r"(dst), "l"(src), "r"(mb) : "memory");
}

// Hierarchical grid barrier
__device__ __forceinline__ void grid_bar() {
    __syncthreads();
    if (threadIdx.x == 0) {
        __threadfence();
        unsigned gen = g_gen;
        if (atomicInc(&g_cnt_sub[(blockIdx.x & (NGRP - 1)) * 32],
                      NBLK / NGRP - 1) == NBLK / NGRP - 1) {
            if (atomicInc(&g_cnt_top, NGRP - 1) == NGRP - 1) g_gen = gen + 1;
        }
        while (g_gen == gen) __nanosleep(32);
        __threadfence();
    }
    __syncthreads();
}

__device__ __forceinline__ int skw(int r) { return ((r >> 3) & 7) * 4; }

// ---------------------------------------------------------------------------
// Job & staging (1KB cp.async.bulk rows into double-buffered smem)
// Weight smem row r -> global row j0 + (r&7) + (r>>3)*GS.
// ---------------------------------------------------------------------------
struct Job {
    const float *Xa, *Xb, *Wa, *Wb;
    const int* toks;
    size_t ldw;
    int j0, GS, nw, npk;
};
struct Bufs {
    float *xb0, *xb1, *wb0, *wb1;
    unsigned mb0, mb1;
};

__device__ __forceinline__ void stage_w(const Bufs& Bf, const Job& J, int p, int tid) {
    const int s = p & 1;
    const unsigned mb = s ? Bf.mb1 : Bf.mb0;
    float* wb = s ? Bf.wb1 : Bf.wb0;
    if (tid == 0) mb_expect(mb, (unsigned)(32 + J.nw) * 1024u);
    __syncthreads();   // all warps done reading this buffer pair
    if (tid >= 32 && tid < 32 + J.nw) {
        int r = tid - 32;
        const float* W = (p >= 4) ? J.Wb : J.Wa;
        int k0 = (p & 3) * KP;
        bulk1k(su32(wb + r * XST + skw(r)),
               W + (size_t)(J.j0 + (r & 7) + (r >> 3) * J.GS) * J.ldw + k0, mb);
    }
}
__device__ __forceinline__ void stage_x(const Bufs& Bf, const Job& J, int p, int tid) {
    const int s = p & 1;
    const unsigned mb = s ? Bf.mb1 : Bf.mb0;
    float* xb = s ? Bf.xb1 : Bf.xb0;
    if (tid < 32) {
        const float* X = (p >= 4) ? J.Xb : J.Xa;
        int k0 = (p & 3) * KP;
        const float* src = J.toks ? X + (size_t)J.toks[tid] * H_ + k0
                                  : X + (size_t)tid * H_ + k0;
        bulk1k(su32(xb + tid * XST + skw(tid)), src, mb);
    }
}

// 32-row compute, 16 warps: warp = (ks = wid&7 k-slice of 32, rh = wid>>3);
// thread tile 8 rows x 2 batches.
__device__ __forceinline__ void comp32(const float* xb, const float* wb,
                                       unsigned long long* acc, int wid, int lane) {
    const int ks = wid & 7, rh = wid >> 3;
    const int bp = lane & 15, rg = lane >> 4;
    const int R0 = rh * 16 + rg * 8;
    const float* xp0 = xb + (2 * bp) * XST + skw(2 * bp) + ks * 32;
    const float* wp  = wb + R0 * XST + skw(R0) + ks * 32;
#pragma unroll
    for (int kq = 0; kq < 32; kq += 4) {
        ulonglong2 x0 = *(const ulonglong2*)(xp0 + kq);
        ulonglong2 x1 = *(const ulonglong2*)(xp0 + XST + kq);
#pragma unroll
        for (int r = 0; r < 8; r++) {
            ulonglong2 wv = *(const ulonglong2*)(wp + r * XST + kq);
            FMA2(acc[2 * r],     x0.x, wv.x); FMA2(acc[2 * r],     x0.y, wv.y);
            FMA2(acc[2 * r + 1], x1.x, wv.x); FMA2(acc[2 * r + 1], x1.y, wv.y);
        }
    }
}
// 8-row compute, 16 warps: warp = k-slice of 16 (wid), lane kk splits 2x8k.
__device__ __forceinline__ void comp8(const float* xb, const float* wb,
                                      unsigned long long* acc, int wid, int lane) {
    const int bp = lane & 15, kk = lane >> 4;
    const int ko = wid * 16 + kk * 8;
    const float* xp0 = xb + (2 * bp) * XST + skw(2 * bp) + ko;
    const float* wp  = wb + ko;
#pragma unroll
    for (int kq = 0; kq < 8; kq += 4) {
        ulonglong2 x0 = *(const ulonglong2*)(xp0 + kq);
        ulonglong2 x1 = *(const ulonglong2*)(xp0 + XST + kq);
#pragma unroll
        for (int r = 0; r < 8; r++) {
            ulonglong2 wv = *(const ulonglong2*)(wp + r * XST + kq);
            FMA2(acc[2 * r],     x0.x, wv.x); FMA2(acc[2 * r],     x0.y, wv.y);
            FMA2(acc[2 * r + 1], x1.x, wv.x); FMA2(acc[2 * r + 1], x1.y, wv.y);
        }
    }
}

// Run a job; last two passes prestage nextJ's passes 0,1.
template <bool W32>
__device__ void run_job(const Bufs& Bf, const Job& J, const Job* nextJ, bool nextX,
                        unsigned long long* acc, unsigned* ph,
                        int tid, int wid, int lane) {
    for (int p = 0; p < J.npk; p++) {
        const int s = p & 1;
        const unsigned mb = s ? Bf.mb1 : Bf.mb0;
        mb_wait(mb, ph[s] & 1);
        ph[s]++;
        const float* xb = s ? Bf.xb1 : Bf.xb0;
        const float* wb = s ? Bf.wb1 : Bf.wb0;
        if (W32) comp32(xb, wb, acc, wid, lane);
        else     comp8(xb, wb, acc, wid, lane);
        if (p + 2 < J.npk) {
            stage_w(Bf, J, p + 2, tid);
            stage_x(Bf, J, p + 2, tid);
        } else if (nextJ) {
            int q = p + 2 - J.npk;
            stage_w(Bf, *nextJ, q, tid);
            if (nextX) stage_x(Bf, *nextJ, q, tid);
        }
    }
}

// Reductions (dedicated red region)
__device__ __forceinline__ void red_write32(float* red, const unsigned long long* acc,
                                            int wid, int lane) {
    const int ks = wid & 7, rh = wid >> 3, bp = lane & 15, rg = lane >> 4;
    const int R0 = rh * 16 + rg * 8;
#pragma unroll
    for (int r = 0; r < 8; r++) {
        float2 v = make_float2(unpack_sum(acc[2 * r]), unpack_sum(acc[2 * r + 1]));
        *(float2*)&red[ks * 1024 + (R0 + r) * 32 + 2 * bp] = v;
    }
}
__device__ __forceinline__ float red_sum32(const float* red, int row, int b) {
    float s = 0.f;
#pragma unroll
    for (int i = 0; i < 8; i++) s += red[i * 1024 + row * 32 + b];
    return s;
}
__device__ __forceinline__ void red_write8(float* red, const unsigned long long* acc,
                                           int wid, int lane) {
    const int bp = lane & 15, kk = lane >> 4;
    const int sl = wid * 2 + kk;
#pragma unroll
    for (int r = 0; r < 8; r++) {
        float2 v = make_float2(unpack_sum(acc[2 * r]), unpack_sum(acc[2 * r + 1]));
        *(float2*)&red[sl * 256 + r * 32 + 2 * bp] = v;
    }
}
__device__ __forceinline__ float red_sum8(const float* red, int row, int b) {
    float s = 0.f;
#pragma unroll
    for (int i = 0; i < 32; i++) s += red[i * 256 + row * 32 + b];
    return s;
}

// ===========================================================================
// Persistent step kernel. grid NBLK x 512.
// Per step: cell0 |B| cell1 |B| gamma |B| out_h1 + attn |B| out_ctx
// ===========================================================================
__global__ void __launch_bounds__(NT_, 1) k_steps(const float* __restrict__ Whh0,
                                                  const float* __restrict__ Wih1,
                                                  const float* __restrict__ Whh1,
                                                  const float* __restrict__ bih1,
                                                  const float* __restrict__ bhh1,
                                                  const float* __restrict__ W_in,
                                                  const float* __restrict__ b_in,
                                                  const float* __restrict__ W_out,
                                                  const float* __restrict__ b_out,
                                                  const float* __restrict__ contexts,
                                                  float* __restrict__ out) {
    extern __shared__ float sm[];
    __shared__ unsigned long long mbar[2];
    __shared__ float gs[H_];
    __shared__ float w_sh[S_];
    const int tid = threadIdx.x, wid = tid >> 5, lane = tid & 31;
    const int blk = blockIdx.x;
    const int jl = tid >> 5, b = tid & 31;   // epilogue map (tid<256)
    const int j = blk * 8 + jl;
    float* red = sm + 4 * BUF;

    if (tid == 0) { mb_init(&mbar[0]); mb_init(&mbar[1]); }
    __syncthreads();
    Bufs Bf = {sm, sm + 2 * BUF, sm + BUF, sm + 3 * BUF,
               su32(&mbar[0]), su32(&mbar[1])};
    unsigned ph[2] = {0u, 0u};

    // pre-loop: fully stage cell0(t=0)
    {
        Job C0 = {&g_hbuf[1][0][0][0], nullptr, Whh0, nullptr, nullptr,
                  (size_t)H_, blk * 8, H_, 32, 4};
        stage_w(Bf, C0, 0, tid); stage_x(Bf, C0, 0, tid);
        stage_w(Bf, C0, 1, tid); stage_x(Bf, C0, 1, tid);
    }

    for (int t = 0; t < T_; t++) {
        const int cur = t & 1;

        Job C0 = {&g_hbuf[1 - cur][0][0][0], nullptr, Whh0, nullptr, nullptr,
                  (size_t)H_, blk * 8, H_, 32, 4};
        Job C1 = {&g_hbuf[cur][0][0][0], &g_hbuf[1 - cur][1][0][0],
                  Wih1, Whh1, nullptr, (size_t)H_, blk * 8, H_, 32, 8};
        Job GM = {&g_hbuf[cur][1][0][0], nullptr, W_in, nullptr, nullptr,
                  (size_t)H_, blk * 8, 8, 8, 4};
        Job OA = {&g_hbuf[cur][1][0][0], nullptr, W_out + H_, nullptr, nullptr,
                  (size_t)(2 * H_), blk * 8, 8, 8, 4};
        Job OB = {&g_ctx[0][0], nullptr, W_out, nullptr, nullptr,
                  (size_t)(2 * H_), blk * 8, 8, 8, 4};
        Job C0n = {&g_hbuf[cur][0][0][0], nullptr, Whh0, nullptr, nullptr,
                   (size_t)H_, blk * 8, H_, 32, 4};

        // ---- P1: cell0; prestage C1 weights ----
        {
            unsigned long long acc[16] = {};
            run_job<true>(Bf, C0, &C1, false, acc, ph, tid, wid, lane);
            red_write32(red, acc, wid, lane);
            __syncthreads();
            if (tid < 256) {
                const float* pre = g_pre0 + (size_t)t * G_ * B_;
                float v[4];
#pragma unroll
                for (int g = 0; g < 4; g++)
                    v[g] = red_sum32(red, g * 8 + jl, b) +
                           pre[(size_t)(g * H_ + j) * B_ + b];
                float c1 = sigf(v[1]) * g_c[0][b][j] + sigf(v[0]) * tanhf(v[2]);
                g_c[0][b][j] = c1;
                g_hbuf[cur][0][b][j] = sigf(v[3]) * tanhf(c1);
            }
        }
        grid_bar();

        // ---- P2: cell1 (x published now); prestage gamma weights ----
        {
            stage_x(Bf, C1, 0, tid);
            stage_x(Bf, C1, 1, tid);
            unsigned long long acc[16] = {};
            run_job<true>(Bf, C1, &GM, false, acc, ph, tid, wid, lane);
            red_write32(red, acc, wid, lane);
            __syncthreads();
            if (tid < 256) {
                float v[4];
#pragma unroll
                for (int g = 0; g < 4; g++)
                    v[g] = red_sum32(red, g * 8 + jl, b) +
                           bih1[g * H_ + j] + bhh1[g * H_ + j];
                float c1 = sigf(v[1]) * g_c[1][b][j] + sigf(v[0]) * tanhf(v[2]);
                g_c[1][b][j] = c1;
                g_hbuf[cur][1][b][j] = sigf(v[3]) * tanhf(c1);
            }
        }
        grid_bar();

        // ---- P3: gamma; prestage out_h1 fully (x = h1 published) ----
        {
            stage_x(Bf, GM, 0, tid);
            stage_x(Bf, GM, 1, tid);
            unsigned long long acc[16] = {};
            run_job<false>(Bf, GM, &OA, true, acc, ph, tid, wid, lane);
            red_write8(red, acc, wid, lane);
            __syncthreads();
            if (tid < 256) g_gamma[b][j] = red_sum8(red, jl, b) + b_in[j];
        }
        grid_bar();

        // ---- P4: out h1-half GEMM (prestage OB weights); attn on blocks 0..31 ----
        unsigned long long oacc[16] = {};
        run_job<false>(Bf, OA, &OB, false, oacc, ph, tid, wid, lane);
        if (blk < B_) {
            const int bb = blk;
            for (int i = tid; i < H_; i += NT_) gs[i] = g_gamma[bb][i];
            __syncthreads();
#pragma unroll
            for (int si = 0; si < 4; si++) {
                int s = wid * 4 + si;
                const float* cp = contexts + ((size_t)bb * S_ + s) * H_;
                float a = 0.f;
                for (int k = lane; k < H_; k += 32) a = fmaf(cp[k], gs[k], a);
#pragma unroll
                for (int o = 16; o; o >>= 1) a += __shfl_xor_sync(0xffffffffu, a, o);
                if (lane == 0) w_sh[s] = a;
            }
            __syncthreads();
            if (wid == 0) {
                float v0 = w_sh[lane], v1 = w_sh[lane + 32];
                float m = fmaxf(v0, v1);
#pragma unroll
                for (int o = 16; o; o >>= 1) m = fmaxf(m, __shfl_xor_sync(0xffffffffu, m, o));
                float e0 = expf(v0 - m), e1 = expf(v1 - m);
                float ssum = e0 + e1;
#pragma unroll
                for (int o = 16; o; o >>= 1) ssum += __shfl_xor_sync(0xffffffffu, ssum, o);
                float inv = 1.f / ssum;
                w_sh[lane] = e0 * inv;
                w_sh[lane + 32] = e1 * inv;
            }
            __syncthreads();
#pragma unroll
            for (int i = 0; i < H_ / NT_; i++) {
                int k = tid + i * NT_;
                const float* cp = contexts + (size_t)bb * S_ * H_ + k;
                float a = 0.f;
#pragma unroll 8
                for (int s = 0; s < S_; s++) a = fmaf(w_sh[s], cp[(size_t)s * H_], a);
                g_ctx[bb][k] = a;
            }
        }
        grid_bar();

        // ---- P5: out ctx-half; prestage next cell0 fully; epilogue ----
        {
            stage_x(Bf, OB, 0, tid);
            stage_x(Bf, OB, 1, tid);
            run_job<false>(Bf, OB, (t + 1 < T_) ? &C0n : nullptr, true,
                           oacc, ph, tid, wid, lane);
            __syncthreads();
            red_write8(red, oacc, wid, lane);
            __syncthreads();
            if (tid < 256)
                out[(size_t)t * B_ * H_ + (size_t)b * H_ + j] =
                    tanhf(red_sum8(red, jl, b) + b_out[j]);
        }
        // no grid_bar: C0n inputs stable; g_ctx rewritten after >=3 bars of t+1
    }
}

// ===========================================================================
// pre0: grid (G/32, T) x 512. 32-row GEMM with embedding gather.
// ===========================================================================
__global__ void __launch_bounds__(NT_, 1) k_pre0(const int* __restrict__ tokens,
                                                 const float* __restrict__ emb,
                                                 const float* __restrict__ Wih0,
                                                 const float* __restrict__ bih0,
                                                 const float* __restrict__ bhh0) {
    extern __shared__ float sm[];
    __shared__ unsigned long long mbar[2];
    __shared__ int toks[B_];
    const int tid = threadIdx.x, wid = tid >> 5, lane = tid & 31;
    const int t = blockIdx.y;
    const int j0 = blockIdx.x * 32;
    float* red = sm + 4 * BUF;

    if (tid == 0) { mb_init(&mbar[0]); mb_init(&mbar[1]); }
    if (tid < B_) toks[tid] = tokens[t * B_ + tid];
    __syncthreads();
    Bufs Bf = {sm, sm + 2 * BUF, sm + BUF, sm + 3 * BUF,
               su32(&mbar[0]), su32(&mbar[1])};
    unsigned ph[2] = {0u, 0u};

    Job P = {emb, nullptr, Wih0, nullptr, toks, (size_t)H_, j0, 8, 32, 4};
    stage_w(Bf, P, 0, tid); stage_x(Bf, P, 0, tid);
    stage_w(Bf, P, 1, tid); stage_x(Bf, P, 1, tid);

    unsigned long long acc[16] = {};
    run_job<true>(Bf, P, nullptr, false, acc, ph, tid, wid, lane);
    __syncthreads();
    red_write32(red, acc, wid, lane);
    __syncthreads();

    const int rl = tid >> 5, b = tid & 31;
#pragma unroll
    for (int i = 0; i < 2; i++) {
        int row = rl + i * 16;
        int jj = j0 + row;
        g_pre0[((size_t)t * G_ + jj) * B_ + b] =
            red_sum32(red, row, b) + bih0[jj] + bhh0[jj];
    }
}

// ---------------------------------------------------------------------------
extern "C" void kernel_launch(void* const* d_in, const int* in_sizes, int n_in,
                              void* d_out, int out_size) {
    const int*   tokens   = (const int*)d_in[0];
    const float* h0       = (const float*)d_in[1];
    const float* c0       = (const float*)d_in[2];
    const float* contexts = (const float*)d_in[3];
    const float* emb      = (const float*)d_in[4];
    const float* W_ih     = (const float*)d_in[5];
    const float* W_hh     = (const float*)d_in[6];
    const float* b_ih     = (const float*)d_in[7];
    const float* b_hh     = (const float*)d_in[8];
    const float* W_in     = (const float*)d_in[9];
    const float* b_in     = (const float*)d_in[10];
    const float* W_out    = (const float*)d_in[11];
    const float* b_out    = (const float*)d_in[12];
    float* out = (float*)d_out;

    cudaFuncSetAttribute(k_pre0,  cudaFuncAttributeMaxDynamicSharedMemorySize, SMEM_BYTES);
    cudaFuncSetAttribute(k_steps, cudaFuncAttributeMaxDynamicSharedMemorySize, SMEM_BYTES);

    const size_t stateBytes = (size_t)L_ * B_ * H_ * sizeof(float);

    // init state: h -> hbuf[1] (prev of t=0), c -> g_c
    cudaMemcpyToSymbolAsync(g_hbuf, h0, stateBytes, stateBytes,
                            cudaMemcpyDeviceToDevice, 0);
    cudaMemcpyToSymbolAsync(g_c, c0, stateBytes, 0, cudaMemcpyDeviceToDevice, 0);

    // hoisted layer-0 input projection for all timesteps
    k_pre0<<<dim3(G_ / 32, T_), NT_, SMEM_BYTES>>>(tokens, emb, W_ih, b_ih, b_hh);

    const float* Wih1 = W_ih + (size_t)G_ * H_;
    const float* Whh1 = W_hh + (size_t)G_ * H_;
    const float* bih1 = b_ih + G_;
    const float* bhh1 = b_hh + G_;

    // entire recurrence in ONE persistent kernel
    k_steps<<<NBLK, NT_, SMEM_BYTES>>>(W_hh, Wih1, Whh1, bih1, bhh1,
                                       W_in, b_in, W_out, b_out, contexts, out);

    // hT (in hbuf[1] since (T-1)&1 == 1), then cT
    cudaMemcpyFromSymbolAsync(out + (size_t)T_ * B_ * H_, g_hbuf, stateBytes,
                              stateBytes, cudaMemcpyDeviceToDevice, 0);
    cudaMemcpyFromSymbolAsync(out + (size_t)T_ * B_ * H_ + (size_t)L_ * B_ * H_,
                              g_c, stateBytes, 0, cudaMemcpyDeviceToDevice, 0);
}